// round 13
// baseline (speedup 1.0000x reference)
#include <cuda_runtime.h>
#include <cuda_bf16.h>
#include <math.h>
#include <stdint.h>

#define T_TOT 32768
#define DM    256
#define FFN   1024

// ---------------- scratch (allocation-free rule) ---------------------------
__device__ float g_xT  [(size_t)DM * T_TOT];      // x^T [256][32768] fp32
__device__ float g_WtT [(size_t)DM * FFN];        // Wt^T [256][1024] fp32
__device__ __nv_bfloat16 g_xh [(size_t)T_TOT * DM];  // x hi [32768][256]
__device__ __nv_bfloat16 g_xl [(size_t)T_TOT * DM];
__device__ __nv_bfloat16 g_Wch[(size_t)FFN * DM];    // Wc^T hi [1024][256]
__device__ __nv_bfloat16 g_Wcl[(size_t)FFN * DM];
__device__ __nv_bfloat16 g_Wgh[(size_t)FFN * DM];
__device__ __nv_bfloat16 g_Wgl[(size_t)FFN * DM];
__device__ __nv_bfloat16 g_fh [(size_t)T_TOT * FFN]; // fused hi [32768][1024]
__device__ __nv_bfloat16 g_fl [(size_t)T_TOT * FFN]; // fused lo
__device__ __nv_bfloat16 g_Wdh[(size_t)DM * FFN];    // Wd^T hi [256][1024]
__device__ __nv_bfloat16 g_Wdl[(size_t)DM * FFN];

__device__ __forceinline__ float sigf(float z) { return 1.0f / (1.0f + __expf(-z)); }
__device__ __forceinline__ unsigned long long pack2(float lo, float hi) {
    unsigned long long r; asm("mov.b64 %0, {%1, %2};" : "=l"(r) : "f"(lo), "f"(hi)); return r;
}
__device__ __forceinline__ void unpack2(unsigned long long v, float& lo, float& hi) {
    asm("mov.b64 {%0, %1}, %2;" : "=f"(lo), "=f"(hi) : "l"(v));
}
__device__ __forceinline__ unsigned long long add2(unsigned long long a, unsigned long long b) {
    unsigned long long d; asm("add.rn.f32x2 %0, %1, %2;" : "=l"(d) : "l"(a), "l"(b)); return d;
}
__device__ __forceinline__ void cp16(uint32_t s, const void* g) {
    asm volatile("cp.async.cg.shared.global [%0], [%1], 16;" :: "r"(s), "l"(g));
}
__device__ __forceinline__ void cp_commit() { asm volatile("cp.async.commit_group;" ::: "memory"); }
template <int N> __device__ __forceinline__ void cp_wait() {
    asm volatile("cp.async.wait_group %0;" :: "n"(N) : "memory");
}
__device__ __forceinline__ void ldsm4(uint32_t* r, uint32_t a) {
    asm volatile("ldmatrix.sync.aligned.m8n8.x4.shared.b16 {%0,%1,%2,%3}, [%4];"
                 : "=r"(r[0]), "=r"(r[1]), "=r"(r[2]), "=r"(r[3]) : "r"(a));
}
__device__ __forceinline__ void ldsm2(uint32_t* r, uint32_t a) {
    asm volatile("ldmatrix.sync.aligned.m8n8.x2.shared.b16 {%0,%1}, [%2];"
                 : "=r"(r[0]), "=r"(r[1]) : "r"(a));
}
__device__ __forceinline__ void mma_bf16(float* d, const uint32_t* a, const uint32_t* b) {
    asm volatile("mma.sync.aligned.m16n8k16.row.col.f32.bf16.bf16.f32 "
                 "{%0,%1,%2,%3}, {%4,%5,%6,%7}, {%8,%9}, {%0,%1,%2,%3};"
                 : "+f"(d[0]), "+f"(d[1]), "+f"(d[2]), "+f"(d[3])
                 : "r"(a[0]), "r"(a[1]), "r"(a[2]), "r"(a[3]), "r"(b[0]), "r"(b[1]));
}

// ---------------- prep kernels ---------------------------------------------
__global__ void transpose_kernel(const float* __restrict__ in, float* __restrict__ out, int R, int C) {
    __shared__ float t[32][33];
    const int bx = blockIdx.x * 32, by = blockIdx.y * 32;
    const int x = threadIdx.x, y = threadIdx.y;
#pragma unroll
    for (int i = 0; i < 32; i += 8) t[y + i][x] = in[(size_t)(by + y + i) * C + bx + x];
    __syncthreads();
#pragma unroll
    for (int i = 0; i < 32; i += 8) out[(size_t)(bx + y + i) * R + by + x] = t[x][y + i];
}
__global__ void split_bf16_kernel(const float4* __restrict__ in,
                                  __nv_bfloat16* __restrict__ oh,
                                  __nv_bfloat16* __restrict__ ol, int n4) {
    const int i = blockIdx.x * blockDim.x + threadIdx.x;
    if (i >= n4) return;
    float4 v = in[i];
    __nv_bfloat16 h[4], l[4];
    const float vv[4] = {v.x, v.y, v.z, v.w};
#pragma unroll
    for (int k = 0; k < 4; k++) {
        h[k] = __float2bfloat16(vv[k]);
        l[k] = __float2bfloat16(vv[k] - __bfloat162float(h[k]));
    }
    *(uint2*)(oh + (size_t)i * 4) = *(const uint2*)h;
    *(uint2*)(ol + (size_t)i * 4) = *(const uint2*)l;
}
__global__ void transpose_split_bf16_kernel(const float* __restrict__ in,
                                            __nv_bfloat16* __restrict__ oh,
                                            __nv_bfloat16* __restrict__ ol,
                                            int R, int C) {
    __shared__ float t[32][33];
    const int bx = blockIdx.x * 32, by = blockIdx.y * 32;
    const int x = threadIdx.x, y = threadIdx.y;
#pragma unroll
    for (int i = 0; i < 32; i += 8) t[y + i][x] = in[(size_t)(by + y + i) * C + bx + x];
    __syncthreads();
#pragma unroll
    for (int i = 0; i < 32; i += 8) {
        const float v = t[x][y + i];
        const __nv_bfloat16 h = __float2bfloat16(v);
        const __nv_bfloat16 l = __float2bfloat16(v - __bfloat162float(h));
        oh[(size_t)(bx + y + i) * R + by + x] = h;
        ol[(size_t)(bx + y + i) * R + by + x] = l;
    }
}

// ---------------- merged kernel: tropical + HMMA GEMMs + epilogue -----------
// tile 128 tok x 64 j; 256 threads; 1 CTA/SM; 8 chunks of 32 k.
// smem per buffer (bytes):
//   XH_O 0      (128 rows x 80B)   = 10240   bf16 x hi, token-major for ldsm
//   XL_O 10240                      = 10240
//   B_O  20480  (4 mats x 64 x 80) = 20480   Wc/Wg hi/lo
//   XF_O 40960  (32 k x 132 fp32)  = 16896   x fp32, k-major for trop
//   WF_O 57856  (32 k x 68 fp32)   = 8704    Wt fp32, k-major
//   BUF = 66560; two buffers = 133120
// epilogue reuse: TST 0 (64x132 fp32 = 33792), STH 33792, STL 52224
#define MG_RS   80
#define XH_O    0
#define XL_O    10240
#define B_O     20480
#define B_SZ    5120
#define XF_O    40960
#define WF_O    57856
#define MG_BUF  66560
#define MG_SMEM 133120
#define TST_O   0
#define STH_O   33792
#define STL_O   52224

__global__ __launch_bounds__(256, 1) void dtn_mid_kernel(
    const float* __restrict__ bt,
    const float* __restrict__ sl_cvx, const float* __restrict__ of_cvx,
    const float* __restrict__ sl_ccv, const float* __restrict__ of_ccv,
    const float* __restrict__ alpha,  const float* __restrict__ bc,
    const float* __restrict__ bg)
{
    extern __shared__ char dsm[];
    float* dsmf = (float*)dsm;
    const int tid  = threadIdx.x;
    const int wid  = tid >> 5;
    const int lane = tid & 31;
    const int tx   = tid & 15;     // trop: j quad
    const int ty   = tid >> 4;     // trop: token group of 8
    const int n0   = blockIdx.x * 64;
    const int m0   = blockIdx.y * 128;
    const int wm   = wid & 3;      // HMMA token group
    const int wj   = wid >> 2;     // HMMA j group
    const uint32_t smb = (uint32_t)__cvta_generic_to_shared(dsm);

    const __nv_bfloat16* bmat[4] = {g_Wch, g_Wcl, g_Wgh, g_Wgl};

    auto load_chunk = [&](int ch) {
        const int kc = ch * 32;
        const uint32_t bb = smb + (uint32_t)((ch & 1) * MG_BUF);
        // A bf16 hi/lo: token-major (4 cp16/thread)
#pragma unroll
        for (int i = 0; i < 4; i++) {
            const int idx = tid + i * 256;
            const int split = idx >> 9;
            const int rem = idx & 511, row = rem >> 2, seg = rem & 3;
            const __nv_bfloat16* src = (split ? g_xl : g_xh) +
                (size_t)(m0 + row) * DM + kc + seg * 8;
            cp16(bb + (split ? XL_O : XH_O) + row * MG_RS + seg * 16, src);
        }
        // B bf16: 4 mats (4 cp16/thread)
#pragma unroll
        for (int i = 0; i < 4; i++) {
            const int idx = tid + i * 256;
            const int mat = idx >> 8;
            const int rem = idx & 255, row = rem >> 2, seg = rem & 3;
            cp16(bb + B_O + mat * B_SZ + row * MG_RS + seg * 16,
                 bmat[mat] + (size_t)(n0 + row) * DM + kc + seg * 8);
        }
        // x fp32 k-major: 32 rows x 128 floats (4 cp16/thread)
#pragma unroll
        for (int i = 0; i < 4; i++) {
            const int idx = tid + i * 256;
            const int krow = idx >> 5, col = idx & 31;
            cp16(bb + XF_O + (uint32_t)(krow * 132 + col * 4) * 4,
                 g_xT + (size_t)(kc + krow) * T_TOT + m0 + col * 4);
        }
        // Wt fp32 k-major: 32 rows x 64 floats (2 cp16/thread)
#pragma unroll
        for (int i = 0; i < 2; i++) {
            const int idx = tid + i * 256;
            const int krow = idx >> 4, col = idx & 15;
            cp16(bb + WF_O + (uint32_t)(krow * 68 + col * 4) * 4,
                 g_WtT + (size_t)(kc + krow) * FFN + n0 + col * 4);
        }
    };

    const float NEG_INF = __int_as_float(0xff800000);
    float tmax[8][4];
    float cacc[2][4][4], gacc[2][4][4];
#pragma unroll
    for (int i = 0; i < 8; i++)
#pragma unroll
        for (int j = 0; j < 4; j++) tmax[i][j] = NEG_INF;
#pragma unroll
    for (int mt = 0; mt < 2; mt++)
#pragma unroll
        for (int nt = 0; nt < 4; nt++)
#pragma unroll
            for (int v = 0; v < 4; v++) { cacc[mt][nt][v] = 0.0f; gacc[mt][nt][v] = 0.0f; }

    load_chunk(0); cp_commit();
    load_chunk(1); cp_commit();

    for (int ch = 0; ch < 8; ch++) {
        if (ch < 7) cp_wait<1>(); else cp_wait<0>();
        __syncthreads();
        const uint32_t bb = smb + (uint32_t)((ch & 1) * MG_BUF);
        const float* bfx = (const float*)(dsm + (ch & 1) * MG_BUF + XF_O);
        const float* bfw = (const float*)(dsm + (ch & 1) * MG_BUF + WF_O);

        // ---- tropical SIMT sub-loop (fma: add2, alu: FMNMX) ----
#pragma unroll
        for (int kk = 0; kk < 32; kk++) {
            const float* xrow = bfx + kk * 132;
            const float* wrow = bfw + kk * 68;
            const ulonglong2 xp01 = *(const ulonglong2*)(xrow + ty * 8);
            const ulonglong2 xp23 = *(const ulonglong2*)(xrow + ty * 8 + 4);
            const unsigned long long xp[4] = {xp01.x, xp01.y, xp23.x, xp23.y};
            const float4 wa = *(const float4*)(wrow + tx * 4);
            const float wn[4] = {wa.x, wa.y, wa.z, wa.w};
#pragma unroll
            for (int ni = 0; ni < 4; ni++) {
                const unsigned long long wd2 = pack2(wn[ni], wn[ni]);
#pragma unroll
                for (int mp = 0; mp < 4; mp++) {
                    float lo, hi;
                    unpack2(add2(xp[mp], wd2), lo, hi);
                    tmax[mp*2+0][ni] = fmaxf(tmax[mp*2+0][ni], lo);
                    tmax[mp*2+1][ni] = fmaxf(tmax[mp*2+1][ni], hi);
                }
            }
        }

        // ---- HMMA block (tensor + LDS pipes) ----
        uint32_t af[2][2][2][4];
#pragma unroll
        for (int sp = 0; sp < 2; sp++)
#pragma unroll
            for (int mt = 0; mt < 2; mt++)
#pragma unroll
                for (int kt = 0; kt < 2; kt++) {
                    const uint32_t a = bb + (sp ? XL_O : XH_O) +
                        (uint32_t)(wm * 32 + mt * 16 + (lane & 15)) * MG_RS +
                        (uint32_t)(kt * 2 + (lane >> 4)) * 16;
                    ldsm4(af[sp][mt][kt], a);
                }
#pragma unroll
        for (int gm = 0; gm < 2; gm++) {
            float (*acc)[4][4] = gm ? gacc : cacc;
#pragma unroll
            for (int nt = 0; nt < 4; nt++) {
                uint32_t bh[2][2], bl[2][2];
#pragma unroll
                for (int kt = 0; kt < 2; kt++) {
                    const uint32_t rowoff =
                        (uint32_t)(wj * 32 + nt * 8 + (lane & 7)) * MG_RS +
                        (uint32_t)(kt * 2 + ((lane >> 3) & 1)) * 16;
                    ldsm2(bh[kt], bb + B_O + (gm * 2 + 0) * B_SZ + rowoff);
                    ldsm2(bl[kt], bb + B_O + (gm * 2 + 1) * B_SZ + rowoff);
                }
#pragma unroll
                for (int mt = 0; mt < 2; mt++)
#pragma unroll
                    for (int kt = 0; kt < 2; kt++) {
                        mma_bf16(acc[mt][nt], af[0][mt][kt], bh[kt]);
                        mma_bf16(acc[mt][nt], af[0][mt][kt], bl[kt]);
                        mma_bf16(acc[mt][nt], af[1][mt][kt], bh[kt]);
                    }
            }
        }
        __syncthreads();
        if (ch + 2 < 8) { load_chunk(ch + 2); cp_commit(); }
    }

    // ---- stage tropical t (with bt) into smem, j-major ---------------------
    __syncthreads();
#pragma unroll
    for (int ni = 0; ni < 4; ni++) {
        const float btj = bt[n0 + tx * 4 + ni];
#pragma unroll
        for (int mi = 0; mi < 8; mi++)
            dsmf[TST_O / 4 + (tx * 4 + ni) * 132 + ty * 8 + mi] = tmax[mi][ni] + btj;
    }
    __syncthreads();

    // ---- epilogue: fused = g*trop + (1-g)*gelu(c) -> bf16 hi/lo ------------
    __nv_bfloat16* sth = (__nv_bfloat16*)(dsm + STH_O);   // [128][72]
    __nv_bfloat16* stl = (__nv_bfloat16*)(dsm + STL_O);
#pragma unroll
    for (int nt = 0; nt < 4; nt++) {
#pragma unroll
        for (int ci = 0; ci < 2; ci++) {
            const int jl = wj * 32 + nt * 8 + ((lane & 3) << 1) + ci;
            const int j  = n0 + jl;
            const float4 sc0 = *(const float4*)(sl_cvx + (size_t)j * 8);
            const float4 sc1 = *(const float4*)(sl_cvx + (size_t)j * 8 + 4);
            const float4 oc0 = *(const float4*)(of_cvx + (size_t)j * 8);
            const float4 oc1 = *(const float4*)(of_cvx + (size_t)j * 8 + 4);
            const float4 sv0 = *(const float4*)(sl_ccv + (size_t)j * 8);
            const float4 sv1 = *(const float4*)(sl_ccv + (size_t)j * 8 + 4);
            const float4 ov0 = *(const float4*)(of_ccv + (size_t)j * 8);
            const float4 ov1 = *(const float4*)(of_ccv + (size_t)j * 8 + 4);
            const float s   = sigf(alpha[j]);
            const float bcj = bc[j];
            const float bgj = bg[j];
#pragma unroll
            for (int mt = 0; mt < 2; mt++)
#pragma unroll
                for (int rh = 0; rh < 2; rh++) {
                    const int tok = wm * 32 + mt * 16 + (lane >> 2) + rh * 8;
                    const float t = dsmf[TST_O / 4 + jl * 132 + tok];
                    float cvx = fmaf(t, sc0.x, oc0.x);
                    cvx = fmaxf(cvx, fmaf(t, sc0.y, oc0.y));
                    cvx = fmaxf(cvx, fmaf(t, sc0.z, oc0.z));
                    cvx = fmaxf(cvx, fmaf(t, sc0.w, oc0.w));
                    cvx = fmaxf(cvx, fmaf(t, sc1.x, oc1.x));
                    cvx = fmaxf(cvx, fmaf(t, sc1.y, oc1.y));
                    cvx = fmaxf(cvx, fmaf(t, sc1.z, oc1.z));
                    cvx = fmaxf(cvx, fmaf(t, sc1.w, oc1.w));
                    float ccv = fmaf(t, sv0.x, ov0.x);
                    ccv = fminf(ccv, fmaf(t, sv0.y, ov0.y));
                    ccv = fminf(ccv, fmaf(t, sv0.z, ov0.z));
                    ccv = fminf(ccv, fmaf(t, sv0.w, ov0.w));
                    ccv = fminf(ccv, fmaf(t, sv1.x, ov1.x));
                    ccv = fminf(ccv, fmaf(t, sv1.y, ov1.y));
                    ccv = fminf(ccv, fmaf(t, sv1.z, ov1.z));
                    ccv = fminf(ccv, fmaf(t, sv1.w, ov1.w));
                    const float trop = s * cvx + (1.0f - s) * ccv;
                    const float cv  = cacc[mt][nt][rh * 2 + ci] + bcj;
                    const float cls = 0.5f * cv * (1.0f + erff(cv * 0.70710678118654752f));
                    const float gv  = sigf(gacc[mt][nt][rh * 2 + ci] + bgj);
                    const float fv  = gv * trop + (1.0f - gv) * cls;
                    const __nv_bfloat16 fh = __float2bfloat16(fv);
                    sth[tok * 72 + jl] = fh;
                    stl[tok * 72 + jl] = __float2bfloat16(fv - __bfloat162float(fh));
                }
        }
    }
    __syncthreads();
#pragma unroll
    for (int r = 0; r < 4; r++) {
        const int idx = tid + r * 256, row = idx >> 3, seg = idx & 7;
        *(uint4*)(g_fh + (size_t)(m0 + row) * FFN + n0 + seg * 8) =
            *(const uint4*)(sth + row * 72 + seg * 8);
        *(uint4*)(g_fl + (size_t)(m0 + row) * FFN + n0 + seg * 8) =
            *(const uint4*)(stl + row * 72 + seg * 8);
    }
}

// ---------------- out kernel: mma.sync bf16 split (R10, unchanged) ----------
#define OD_RS   80
#define OD_AH   0
#define OD_AL   10240
#define OD_BH   20480
#define OD_BL   25600
#define OD_BUF  30720
#define OD_SMEM 61440

__global__ __launch_bounds__(256, 2) void dtn_out_kernel(
    const float* __restrict__ bd, float* __restrict__ out)
{
    extern __shared__ char dsm[];
    const int tid  = threadIdx.x;
    const int wid  = tid >> 5;
    const int lane = tid & 31;
    const int n0   = blockIdx.x * 64;
    const int m0   = blockIdx.y * 128;
    const int wm   = wid & 3;
    const int wj   = wid >> 2;
    const uint32_t smb = (uint32_t)__cvta_generic_to_shared(dsm);

    auto load_chunk = [&](int ch) {
        const int kc = ch * 32;
        const uint32_t bb = smb + (uint32_t)((ch & 1) * OD_BUF);
#pragma unroll
        for (int i = 0; i < 4; i++) {
            const int idx = tid + i * 256;
            const int split = idx >> 9;
            const int rem = idx & 511, row = rem >> 2, seg = rem & 3;
            const __nv_bfloat16* src = (split ? g_fl : g_fh) +
                (size_t)(m0 + row) * FFN + kc + seg * 8;
            cp16(bb + (split ? OD_AL : OD_AH) + row * OD_RS + seg * 16, src);
        }
#pragma unroll
        for (int i = 0; i < 2; i++) {
            const int idx = tid + i * 256;
            const int split = idx >> 8;
            const int rem = idx & 255, row = rem >> 2, seg = rem & 3;
            cp16(bb + (split ? OD_BL : OD_BH) + row * OD_RS + seg * 16,
                 (split ? g_Wdl : g_Wdh) + (size_t)(n0 + row) * FFN + kc + seg * 8);
        }
    };

    float acc[2][4][4];
#pragma unroll
    for (int mt = 0; mt < 2; mt++)
#pragma unroll
        for (int nt = 0; nt < 4; nt++)
#pragma unroll
            for (int v = 0; v < 4; v++) acc[mt][nt][v] = 0.0f;

    load_chunk(0); cp_commit();
    load_chunk(1); cp_commit();

    for (int ch = 0; ch < 32; ch++) {
        if (ch < 31) cp_wait<1>(); else cp_wait<0>();
        __syncthreads();
        const uint32_t bb = smb + (uint32_t)((ch & 1) * OD_BUF);

        uint32_t af[2][2][2][4];
#pragma unroll
        for (int sp = 0; sp < 2; sp++)
#pragma unroll
            for (int mt = 0; mt < 2; mt++)
#pragma unroll
                for (int kt = 0; kt < 2; kt++) {
                    const uint32_t a = bb + (sp ? OD_AL : OD_AH) +
                        (uint32_t)(wm * 32 + mt * 16 + (lane & 15)) * OD_RS +
                        (uint32_t)(kt * 2 + (lane >> 4)) * 16;
                    ldsm4(af[sp][mt][kt], a);
                }
#pragma unroll
        for (int nt = 0; nt < 4; nt++) {
            uint32_t bh[2][2], bl[2][2];
#pragma unroll
            for (int kt = 0; kt < 2; kt++) {
                const uint32_t rowoff =
                    (uint32_t)(wj * 32 + nt * 8 + (lane & 7)) * OD_RS +
                    (uint32_t)(kt * 2 + ((lane >> 3) & 1)) * 16;
                ldsm2(bh[kt], bb + OD_BH + rowoff);
                ldsm2(bl[kt], bb + OD_BL + rowoff);
            }
#pragma unroll
            for (int mt = 0; mt < 2; mt++)
#pragma unroll
                for (int kt = 0; kt < 2; kt++) {
                    mma_bf16(acc[mt][nt], af[0][mt][kt], bh[kt]);
                    mma_bf16(acc[mt][nt], af[0][mt][kt], bl[kt]);
                    mma_bf16(acc[mt][nt], af[1][mt][kt], bh[kt]);
                }
        }
        __syncthreads();
        if (ch + 2 < 32) { load_chunk(ch + 2); cp_commit(); }
    }

    float* stage = (float*)dsm;   // [128][68]
#pragma unroll
    for (int nt = 0; nt < 4; nt++)
#pragma unroll
        for (int ci = 0; ci < 2; ci++) {
            const int col = wj * 32 + nt * 8 + ((lane & 3) << 1) + ci;
            const float bdv = bd[n0 + col];
#pragma unroll
            for (int mt = 0; mt < 2; mt++)
#pragma unroll
                for (int rh = 0; rh < 2; rh++) {
                    const int tok = wm * 32 + mt * 16 + (lane >> 2) + rh * 8;
                    stage[tok * 68 + col] = acc[mt][nt][rh * 2 + ci] + bdv;
                }
        }
    __syncthreads();
#pragma unroll
    for (int r = 0; r < 8; r++) {
        const int idx = tid + r * 256, row = idx >> 4, seg = idx & 15;
        *(float4*)(out + (size_t)(m0 + row) * DM + n0 + seg * 4) =
            *(const float4*)(stage + row * 68 + seg * 4);
    }
}

extern "C" void kernel_launch(void* const* d_in, const int* in_sizes, int n_in,
                              void* d_out, int out_size) {
    const float* x      = (const float*)d_in[0];
    const float* Wt     = (const float*)d_in[1];
    const float* bt     = (const float*)d_in[2];
    const float* sl_cvx = (const float*)d_in[3];
    const float* of_cvx = (const float*)d_in[4];
    const float* sl_ccv = (const float*)d_in[5];
    const float* of_ccv = (const float*)d_in[6];
    const float* alpha  = (const float*)d_in[7];
    const float* Wc     = (const float*)d_in[8];
    const float* bc     = (const float*)d_in[9];
    const float* Wg     = (const float*)d_in[10];
    const float* bg     = (const float*)d_in[11];
    const float* Wd     = (const float*)d_in[12];
    const float* bd     = (const float*)d_in[13];
    float* out = (float*)d_out;

    float *xT, *wtT;
    __nv_bfloat16 *xh, *xl, *wch, *wcl, *wgh, *wgl, *wdh, *wdl;
    cudaGetSymbolAddress((void**)&xT,  g_xT);
    cudaGetSymbolAddress((void**)&wtT, g_WtT);
    cudaGetSymbolAddress((void**)&xh,  g_xh);
    cudaGetSymbolAddress((void**)&xl,  g_xl);
    cudaGetSymbolAddress((void**)&wch, g_Wch);
    cudaGetSymbolAddress((void**)&wcl, g_Wcl);
    cudaGetSymbolAddress((void**)&wgh, g_Wgh);
    cudaGetSymbolAddress((void**)&wgl, g_Wgl);
    cudaGetSymbolAddress((void**)&wdh, g_Wdh);
    cudaGetSymbolAddress((void**)&wdl, g_Wdl);

    static int attr_set = 0;
    if (!attr_set) {
        cudaFuncSetAttribute(dtn_mid_kernel, cudaFuncAttributeMaxDynamicSharedMemorySize, MG_SMEM);
        cudaFuncSetAttribute(dtn_out_kernel, cudaFuncAttributeMaxDynamicSharedMemorySize, OD_SMEM);
        attr_set = 1;
    }

    transpose_kernel<<<dim3(DM / 32, T_TOT / 32), dim3(32, 8)>>>(x, xT, T_TOT, DM);
    transpose_kernel<<<dim3(DM / 32, FFN / 32), dim3(32, 8)>>>(Wt, wtT, FFN, DM);
    split_bf16_kernel<<<(T_TOT * DM / 4 + 255) / 256, 256>>>((const float4*)x, xh, xl, T_TOT * DM / 4);
    transpose_split_bf16_kernel<<<dim3(FFN / 32, DM / 32), dim3(32, 8)>>>(Wc, wch, wcl, DM, FFN);
    transpose_split_bf16_kernel<<<dim3(FFN / 32, DM / 32), dim3(32, 8)>>>(Wg, wgh, wgl, DM, FFN);
    transpose_split_bf16_kernel<<<dim3(DM / 32, FFN / 32), dim3(32, 8)>>>(Wd, wdh, wdl, FFN, DM);

    dtn_mid_kernel<<<dim3(FFN / 64, T_TOT / 128), 256, MG_SMEM>>>(
        bt, sl_cvx, of_cvx, sl_ccv, of_ccv, alpha, bc, bg);
    dtn_out_kernel<<<dim3(DM / 64, T_TOT / 128), 256, OD_SMEM>>>(bd, out);
}

// round 14
// speedup vs baseline: 1.1383x; 1.1383x over previous
#include <cuda_runtime.h>
#include <cuda_fp16.h>
#include <math.h>
#include <stdint.h>

#define T_TOT 32768
#define DM    256
#define FFN   1024

// ---------------- scratch (allocation-free rule) ---------------------------
__device__ float g_xT  [(size_t)DM * T_TOT];      // x^T [256][32768] fp32
__device__ float g_WtT [(size_t)DM * FFN];        // Wt^T [256][1024] fp32
__device__ float g_tT  [(size_t)FFN * T_TOT];     // tropical+bt [1024][32768]
__device__ __half g_xh [(size_t)T_TOT * DM];      // x hi fp16 [32768][256]
__device__ __half g_xl [(size_t)T_TOT * DM];      // x lo fp16
__device__ __half g_Wch[(size_t)FFN * DM];        // Wc^T fp16 [1024][256]
__device__ __half g_Wgh[(size_t)FFN * DM];        // Wg^T fp16
__device__ __half g_fh [(size_t)T_TOT * FFN];     // fused hi fp16 [32768][1024]
__device__ __half g_fl [(size_t)T_TOT * FFN];     // fused lo fp16
__device__ __half g_Wdh[(size_t)DM * FFN];        // Wd^T fp16 [256][1024]

__device__ __forceinline__ float sigf(float z) { return 1.0f / (1.0f + __expf(-z)); }
__device__ __forceinline__ void cp16(uint32_t s, const void* g) {
    asm volatile("cp.async.cg.shared.global [%0], [%1], 16;" :: "r"(s), "l"(g));
}
__device__ __forceinline__ void cp_commit() { asm volatile("cp.async.commit_group;" ::: "memory"); }
template <int N> __device__ __forceinline__ void cp_wait() {
    asm volatile("cp.async.wait_group %0;" :: "n"(N) : "memory");
}
__device__ __forceinline__ void ldsm4(uint32_t* r, uint32_t a) {
    asm volatile("ldmatrix.sync.aligned.m8n8.x4.shared.b16 {%0,%1,%2,%3}, [%4];"
                 : "=r"(r[0]), "=r"(r[1]), "=r"(r[2]), "=r"(r[3]) : "r"(a));
}
__device__ __forceinline__ void ldsm2(uint32_t* r, uint32_t a) {
    asm volatile("ldmatrix.sync.aligned.m8n8.x2.shared.b16 {%0,%1}, [%2];"
                 : "=r"(r[0]), "=r"(r[1]) : "r"(a));
}
__device__ __forceinline__ void mma_f16(float* d, const uint32_t* a, const uint32_t* b) {
    asm volatile("mma.sync.aligned.m16n8k16.row.col.f32.f16.f16.f32 "
                 "{%0,%1,%2,%3}, {%4,%5,%6,%7}, {%8,%9}, {%0,%1,%2,%3};"
                 : "+f"(d[0]), "+f"(d[1]), "+f"(d[2]), "+f"(d[3])
                 : "r"(a[0]), "r"(a[1]), "r"(a[2]), "r"(a[3]), "r"(b[0]), "r"(b[1]));
}

// ---------------- prep kernels ---------------------------------------------
__global__ void transpose_kernel(const float* __restrict__ in, float* __restrict__ out, int R, int C) {
    __shared__ float t[32][33];
    const int bx = blockIdx.x * 32, by = blockIdx.y * 32;
    const int x = threadIdx.x, y = threadIdx.y;
#pragma unroll
    for (int i = 0; i < 32; i += 8) t[y + i][x] = in[(size_t)(by + y + i) * C + bx + x];
    __syncthreads();
#pragma unroll
    for (int i = 0; i < 32; i += 8) out[(size_t)(bx + y + i) * R + by + x] = t[x][y + i];
}
// x fp32 -> hi/lo fp16
__global__ void split_f16_kernel(const float4* __restrict__ in,
                                 __half* __restrict__ oh,
                                 __half* __restrict__ ol, int n4) {
    const int i = blockIdx.x * blockDim.x + threadIdx.x;
    if (i >= n4) return;
    float4 v = in[i];
    __half h[4], l[4];
    const float vv[4] = {v.x, v.y, v.z, v.w};
#pragma unroll
    for (int k = 0; k < 4; k++) {
        h[k] = __float2half(vv[k]);
        l[k] = __float2half(vv[k] - __half2float(h[k]));
    }
    *(uint2*)(oh + (size_t)i * 4) = *(const uint2*)h;
    *(uint2*)(ol + (size_t)i * 4) = *(const uint2*)l;
}
// in[R][C] fp32 -> out [C][R] fp16 (transposed, single precision limb)
__global__ void transpose_f16_kernel(const float* __restrict__ in,
                                     __half* __restrict__ oh, int R, int C) {
    __shared__ float t[32][33];
    const int bx = blockIdx.x * 32, by = blockIdx.y * 32;
    const int x = threadIdx.x, y = threadIdx.y;
#pragma unroll
    for (int i = 0; i < 32; i += 8) t[y + i][x] = in[(size_t)(by + y + i) * C + bx + x];
    __syncthreads();
#pragma unroll
    for (int i = 0; i < 32; i += 8)
        oh[(size_t)(bx + y + i) * R + by + x] = __float2half(t[x][y + i]);
}

// ---------------- tropical kernel (SIMT scalar, R10 version) ----------------
#define K1_ROW 200
#define K1_BUF (16 * K1_ROW)
#define WTO    132
__global__ __launch_bounds__(256, 3) void dtn_trop_kernel(const float* __restrict__ bt) {
    __shared__ float sm[8448];
    const int tid = threadIdx.x, tx = tid & 15, ty = tid >> 4;
    const int m0 = blockIdx.y * 128, n0 = blockIdx.x * 64;
    const uint32_t smb = (uint32_t)__cvta_generic_to_shared(sm);
    const int xrow = tid >> 5, xcol = tid & 31, wrow = tid >> 4, wcol = tid & 15;
    const float* xg  = g_xT  + (size_t)xrow * T_TOT + m0 + xcol * 4;
    const float* wtg = g_WtT + (size_t)wrow * FFN   + n0 + wcol * 4;

    const float NEG_INF = __int_as_float(0xff800000);
    float tmax[8][4];
#pragma unroll
    for (int i = 0; i < 8; i++)
#pragma unroll
        for (int j = 0; j < 4; j++) tmax[i][j] = NEG_INF;

    cp16(smb + (uint32_t)((xrow)     * K1_ROW + xcol * 4) * 4, xg);
    cp16(smb + (uint32_t)((xrow + 8) * K1_ROW + xcol * 4) * 4, xg + (size_t)8 * T_TOT);
    cp16(smb + (uint32_t)(wrow * K1_ROW + WTO + wcol * 4) * 4, wtg);
    cp_commit();

    for (int ch = 0; ch < 16; ch++) {
        const int p = ch & 1;
        if (ch < 15) {
            const uint32_t b = smb + (uint32_t)((1 - p) * K1_BUF) * 4;
            const size_t xo = (size_t)(ch + 1) * 16 * T_TOT, wo = (size_t)(ch + 1) * 16 * FFN;
            cp16(b + (uint32_t)((xrow)     * K1_ROW + xcol * 4) * 4, xg + xo);
            cp16(b + (uint32_t)((xrow + 8) * K1_ROW + xcol * 4) * 4, xg + xo + (size_t)8 * T_TOT);
            cp16(b + (uint32_t)(wrow * K1_ROW + WTO + wcol * 4) * 4, wtg + wo);
            cp_commit(); cp_wait<1>();
        } else cp_wait<0>();
        __syncthreads();
        const float* buf = sm + p * K1_BUF;
#pragma unroll
        for (int kk = 0; kk < 16; kk++) {
            const float* row = buf + kk * K1_ROW;
            const float4 xa0 = *(const float4*)(row + ty * 8);
            const float4 xa1 = *(const float4*)(row + ty * 8 + 4);
            const float4 wa  = *(const float4*)(row + WTO + tx * 4);
            const float xm[8] = {xa0.x, xa0.y, xa0.z, xa0.w, xa1.x, xa1.y, xa1.z, xa1.w};
            const float wn[4] = {wa.x, wa.y, wa.z, wa.w};
#pragma unroll
            for (int mi = 0; mi < 8; mi++)
#pragma unroll
                for (int ni = 0; ni < 4; ni++)
                    tmax[mi][ni] = fmaxf(tmax[mi][ni], xm[mi] + wn[ni]);
        }
        __syncthreads();
    }
#pragma unroll
    for (int ni = 0; ni < 4; ni++) {
        const float btj = bt[n0 + tx * 4 + ni];
#pragma unroll
        for (int mi = 0; mi < 8; mi++)
            sm[(tx * 4 + ni) * 132 + ty * 8 + mi] = tmax[mi][ni] + btj;
    }
    __syncthreads();
#pragma unroll
    for (int r = 0; r < 8; r++) {
        const int idx = tid + r * 256, row = idx >> 5, c = idx & 31;
        *(float4*)(g_tT + (size_t)(n0 + row) * T_TOT + m0 + c * 4) =
            *(const float4*)(sm + row * 132 + c * 4);
    }
}

// ---------------- cg kernel: fp16 2-term mma + epilogue ---------------------
// tile 128 tok x 64 j; 8 warps; 2 CTAs/SM.
// buffer: XH 0 (10240), XL 10240 (10240), B 20480 (2 mats x 5120)
#define CG_RS   80
#define CG_XH   0
#define CG_XL   10240
#define CG_B    20480
#define CG_BSZ  5120
#define CG_BUF  30720
#define CG_SMEM 61440

__global__ __launch_bounds__(256, 2) void dtn_cg_kernel(
    const float* __restrict__ sl_cvx, const float* __restrict__ of_cvx,
    const float* __restrict__ sl_ccv, const float* __restrict__ of_ccv,
    const float* __restrict__ alpha,  const float* __restrict__ bc,
    const float* __restrict__ bg)
{
    extern __shared__ char dsm[];
    const int tid  = threadIdx.x;
    const int wid  = tid >> 5;
    const int lane = tid & 31;
    const int n0   = blockIdx.x * 64;
    const int m0   = blockIdx.y * 128;
    const int wm   = wid & 3;
    const int wj   = wid >> 2;
    const uint32_t smb = (uint32_t)__cvta_generic_to_shared(dsm);

    const __half* bmat[2] = {g_Wch, g_Wgh};

    auto load_chunk = [&](int ch) {
        const int kc = ch * 32;
        const uint32_t bb = smb + (uint32_t)((ch & 1) * CG_BUF);
#pragma unroll
        for (int i = 0; i < 4; i++) {           // A hi/lo
            const int idx = tid + i * 256;
            const int split = idx >> 9;
            const int rem = idx & 511, row = rem >> 2, seg = rem & 3;
            const __half* src = (split ? g_xl : g_xh) +
                (size_t)(m0 + row) * DM + kc + seg * 8;
            cp16(bb + (split ? CG_XL : CG_XH) + row * CG_RS + seg * 16, src);
        }
#pragma unroll
        for (int i = 0; i < 2; i++) {           // B: 2 mats
            const int idx = tid + i * 256;
            const int mat = idx >> 8;
            const int rem = idx & 255, row = rem >> 2, seg = rem & 3;
            cp16(bb + CG_B + mat * CG_BSZ + row * CG_RS + seg * 16,
                 bmat[mat] + (size_t)(n0 + row) * DM + kc + seg * 8);
        }
    };

    float cacc[2][4][4], gacc[2][4][4];
#pragma unroll
    for (int mt = 0; mt < 2; mt++)
#pragma unroll
        for (int nt = 0; nt < 4; nt++)
#pragma unroll
            for (int v = 0; v < 4; v++) { cacc[mt][nt][v] = 0.0f; gacc[mt][nt][v] = 0.0f; }

    load_chunk(0); cp_commit();
    load_chunk(1); cp_commit();

    for (int ch = 0; ch < 8; ch++) {
        if (ch < 7) cp_wait<1>(); else cp_wait<0>();
        __syncthreads();
        const uint32_t bb = smb + (uint32_t)((ch & 1) * CG_BUF);

        uint32_t af[2][2][2][4];     // [split][mt][kt]
#pragma unroll
        for (int sp = 0; sp < 2; sp++)
#pragma unroll
            for (int mt = 0; mt < 2; mt++)
#pragma unroll
                for (int kt = 0; kt < 2; kt++) {
                    const uint32_t a = bb + (sp ? CG_XL : CG_XH) +
                        (uint32_t)(wm * 32 + mt * 16 + (lane & 15)) * CG_RS +
                        (uint32_t)(kt * 2 + (lane >> 4)) * 16;
                    ldsm4(af[sp][mt][kt], a);
                }
#pragma unroll
        for (int gm = 0; gm < 2; gm++) {
            float (*acc)[4][4] = gm ? gacc : cacc;
#pragma unroll
            for (int nt = 0; nt < 4; nt++) {
                uint32_t bh[2][2];
#pragma unroll
                for (int kt = 0; kt < 2; kt++) {
                    const uint32_t rowoff =
                        (uint32_t)(wj * 32 + nt * 8 + (lane & 7)) * CG_RS +
                        (uint32_t)(kt * 2 + ((lane >> 3) & 1)) * 16;
                    ldsm2(bh[kt], bb + CG_B + gm * CG_BSZ + rowoff);
                }
#pragma unroll
                for (int mt = 0; mt < 2; mt++)
#pragma unroll
                    for (int kt = 0; kt < 2; kt++) {
                        mma_f16(acc[mt][nt], af[0][mt][kt], bh[kt]);
                        mma_f16(acc[mt][nt], af[1][mt][kt], bh[kt]);
                    }
            }
        }
        __syncthreads();
        if (ch + 2 < 8) { load_chunk(ch + 2); cp_commit(); }
    }

    // ---- epilogue: fused -> fp16 hi/lo, token-major -----------------------
    __half* sth = (__half*)dsm;          // [128][72]
    __half* stl = sth + 128 * 72;
#pragma unroll
    for (int nt = 0; nt < 4; nt++) {
#pragma unroll
        for (int ci = 0; ci < 2; ci++) {
            const int jl = wj * 32 + nt * 8 + ((lane & 3) << 1) + ci;
            const int j  = n0 + jl;
            const float4 sc0 = *(const float4*)(sl_cvx + (size_t)j * 8);
            const float4 sc1 = *(const float4*)(sl_cvx + (size_t)j * 8 + 4);
            const float4 oc0 = *(const float4*)(of_cvx + (size_t)j * 8);
            const float4 oc1 = *(const float4*)(of_cvx + (size_t)j * 8 + 4);
            const float4 sv0 = *(const float4*)(sl_ccv + (size_t)j * 8);
            const float4 sv1 = *(const float4*)(sl_ccv + (size_t)j * 8 + 4);
            const float4 ov0 = *(const float4*)(of_ccv + (size_t)j * 8);
            const float4 ov1 = *(const float4*)(of_ccv + (size_t)j * 8 + 4);
            const float s   = sigf(alpha[j]);
            const float bcj = bc[j];
            const float bgj = bg[j];
#pragma unroll
            for (int mt = 0; mt < 2; mt++)
#pragma unroll
                for (int rh = 0; rh < 2; rh++) {
                    const int tok = wm * 32 + mt * 16 + (lane >> 2) + rh * 8;
                    const float t = g_tT[(size_t)j * T_TOT + m0 + tok];
                    float cvx = fmaf(t, sc0.x, oc0.x);
                    cvx = fmaxf(cvx, fmaf(t, sc0.y, oc0.y));
                    cvx = fmaxf(cvx, fmaf(t, sc0.z, oc0.z));
                    cvx = fmaxf(cvx, fmaf(t, sc0.w, oc0.w));
                    cvx = fmaxf(cvx, fmaf(t, sc1.x, oc1.x));
                    cvx = fmaxf(cvx, fmaf(t, sc1.y, oc1.y));
                    cvx = fmaxf(cvx, fmaf(t, sc1.z, oc1.z));
                    cvx = fmaxf(cvx, fmaf(t, sc1.w, oc1.w));
                    float ccv = fmaf(t, sv0.x, ov0.x);
                    ccv = fminf(ccv, fmaf(t, sv0.y, ov0.y));
                    ccv = fminf(ccv, fmaf(t, sv0.z, ov0.z));
                    ccv = fminf(ccv, fmaf(t, sv0.w, ov0.w));
                    ccv = fminf(ccv, fmaf(t, sv1.x, ov1.x));
                    ccv = fminf(ccv, fmaf(t, sv1.y, ov1.y));
                    ccv = fminf(ccv, fmaf(t, sv1.z, ov1.z));
                    ccv = fminf(ccv, fmaf(t, sv1.w, ov1.w));
                    const float trop = s * cvx + (1.0f - s) * ccv;
                    const float cv  = cacc[mt][nt][rh * 2 + ci] + bcj;
                    const float cls = 0.5f * cv * (1.0f + erff(cv * 0.70710678118654752f));
                    const float gv  = sigf(gacc[mt][nt][rh * 2 + ci] + bgj);
                    const float fv  = gv * trop + (1.0f - gv) * cls;
                    const __half fh = __float2half(fv);
                    sth[tok * 72 + jl] = fh;
                    stl[tok * 72 + jl] = __float2half(fv - __half2float(fh));
                }
        }
    }
    __syncthreads();
#pragma unroll
    for (int r = 0; r < 4; r++) {
        const int idx = tid + r * 256, row = idx >> 3, seg = idx & 7;
        *(uint4*)(g_fh + (size_t)(m0 + row) * FFN + n0 + seg * 8) =
            *(const uint4*)(sth + row * 72 + seg * 8);
        *(uint4*)(g_fl + (size_t)(m0 + row) * FFN + n0 + seg * 8) =
            *(const uint4*)(stl + row * 72 + seg * 8);
    }
}

// ---------------- out kernel: fp16 2-term mma --------------------------------
#define OD_RS   80
#define OD_AH   0
#define OD_AL   10240
#define OD_BH   20480
#define OD_BUF  25600
#define OD_SMEM 51200

__global__ __launch_bounds__(256, 2) void dtn_out_kernel(
    const float* __restrict__ bd, float* __restrict__ out)
{
    extern __shared__ char dsm[];
    const int tid  = threadIdx.x;
    const int wid  = tid >> 5;
    const int lane = tid & 31;
    const int n0   = blockIdx.x * 64;
    const int m0   = blockIdx.y * 128;
    const int wm   = wid & 3;
    const int wj   = wid >> 2;
    const uint32_t smb = (uint32_t)__cvta_generic_to_shared(dsm);

    auto load_chunk = [&](int ch) {
        const int kc = ch * 32;
        const uint32_t bb = smb + (uint32_t)((ch & 1) * OD_BUF);
#pragma unroll
        for (int i = 0; i < 4; i++) {
            const int idx = tid + i * 256;
            const int split = idx >> 9;
            const int rem = idx & 511, row = rem >> 2, seg = rem & 3;
            const __half* src = (split ? g_fl : g_fh) +
                (size_t)(m0 + row) * FFN + kc + seg * 8;
            cp16(bb + (split ? OD_AL : OD_AH) + row * OD_RS + seg * 16, src);
        }
        {
            const int row = tid >> 2, seg = tid & 3;
            cp16(bb + OD_BH + row * OD_RS + seg * 16,
                 g_Wdh + (size_t)(n0 + row) * FFN + kc + seg * 8);
        }
    };

    float acc[2][4][4];
#pragma unroll
    for (int mt = 0; mt < 2; mt++)
#pragma unroll
        for (int nt = 0; nt < 4; nt++)
#pragma unroll
            for (int v = 0; v < 4; v++) acc[mt][nt][v] = 0.0f;

    load_chunk(0); cp_commit();
    load_chunk(1); cp_commit();

    for (int ch = 0; ch < 32; ch++) {
        if (ch < 31) cp_wait<1>(); else cp_wait<0>();
        __syncthreads();
        const uint32_t bb = smb + (uint32_t)((ch & 1) * OD_BUF);

        uint32_t af[2][2][2][4];
#pragma unroll
        for (int sp = 0; sp < 2; sp++)
#pragma unroll
            for (int mt = 0; mt < 2; mt++)
#pragma unroll
                for (int kt = 0; kt < 2; kt++) {
                    const uint32_t a = bb + (sp ? OD_AL : OD_AH) +
                        (uint32_t)(wm * 32 + mt * 16 + (lane & 15)) * OD_RS +
                        (uint32_t)(kt * 2 + (lane >> 4)) * 16;
                    ldsm4(af[sp][mt][kt], a);
                }
#pragma unroll
        for (int nt = 0; nt < 4; nt++) {
            uint32_t bh[2][2];
#pragma unroll
            for (int kt = 0; kt < 2; kt++) {
                const uint32_t rowoff =
                    (uint32_t)(wj * 32 + nt * 8 + (lane & 7)) * OD_RS +
                    (uint32_t)(kt * 2 + ((lane >> 3) & 1)) * 16;
                ldsm2(bh[kt], bb + OD_BH + rowoff);
            }
#pragma unroll
            for (int mt = 0; mt < 2; mt++)
#pragma unroll
                for (int kt = 0; kt < 2; kt++) {
                    mma_f16(acc[mt][nt], af[0][mt][kt], bh[kt]);
                    mma_f16(acc[mt][nt], af[1][mt][kt], bh[kt]);
                }
        }
        __syncthreads();
        if (ch + 2 < 32) { load_chunk(ch + 2); cp_commit(); }
    }

    float* stage = (float*)dsm;   // [128][68]
#pragma unroll
    for (int nt = 0; nt < 4; nt++)
#pragma unroll
        for (int ci = 0; ci < 2; ci++) {
            const int col = wj * 32 + nt * 8 + ((lane & 3) << 1) + ci;
            const float bdv = bd[n0 + col];
#pragma unroll
            for (int mt = 0; mt < 2; mt++)
#pragma unroll
                for (int rh = 0; rh < 2; rh++) {
                    const int tok = wm * 32 + mt * 16 + (lane >> 2) + rh * 8;
                    stage[tok * 68 + col] = acc[mt][nt][rh * 2 + ci] + bdv;
                }
        }
    __syncthreads();
#pragma unroll
    for (int r = 0; r < 8; r++) {
        const int idx = tid + r * 256, row = idx >> 4, seg = idx & 15;
        *(float4*)(out + (size_t)(m0 + row) * DM + n0 + seg * 4) =
            *(const float4*)(stage + row * 68 + seg * 4);
    }
}

extern "C" void kernel_launch(void* const* d_in, const int* in_sizes, int n_in,
                              void* d_out, int out_size) {
    const float* x      = (const float*)d_in[0];
    const float* Wt     = (const float*)d_in[1];
    const float* bt     = (const float*)d_in[2];
    const float* sl_cvx = (const float*)d_in[3];
    const float* of_cvx = (const float*)d_in[4];
    const float* sl_ccv = (const float*)d_in[5];
    const float* of_ccv = (const float*)d_in[6];
    const float* alpha  = (const float*)d_in[7];
    const float* Wc     = (const float*)d_in[8];
    const float* bc     = (const float*)d_in[9];
    const float* Wg     = (const float*)d_in[10];
    const float* bg     = (const float*)d_in[11];
    const float* Wd     = (const float*)d_in[12];
    const float* bd     = (const float*)d_in[13];
    float* out = (float*)d_out;

    float *xT, *wtT;
    __half *xh, *xl, *wch, *wgh, *wdh;
    cudaGetSymbolAddress((void**)&xT,  g_xT);
    cudaGetSymbolAddress((void**)&wtT, g_WtT);
    cudaGetSymbolAddress((void**)&xh,  g_xh);
    cudaGetSymbolAddress((void**)&xl,  g_xl);
    cudaGetSymbolAddress((void**)&wch, g_Wch);
    cudaGetSymbolAddress((void**)&wgh, g_Wgh);
    cudaGetSymbolAddress((void**)&wdh, g_Wdh);

    static int attr_set = 0;
    if (!attr_set) {
        cudaFuncSetAttribute(dtn_cg_kernel, cudaFuncAttributeMaxDynamicSharedMemorySize, CG_SMEM);
        cudaFuncSetAttribute(dtn_out_kernel, cudaFuncAttributeMaxDynamicSharedMemorySize, OD_SMEM);
        attr_set = 1;
    }

    transpose_kernel<<<dim3(DM / 32, T_TOT / 32), dim3(32, 8)>>>(x, xT, T_TOT, DM);
    transpose_kernel<<<dim3(DM / 32, FFN / 32), dim3(32, 8)>>>(Wt, wtT, FFN, DM);
    split_f16_kernel<<<(T_TOT * DM / 4 + 255) / 256, 256>>>((const float4*)x, xh, xl, T_TOT * DM / 4);
    transpose_f16_kernel<<<dim3(FFN / 32, DM / 32), dim3(32, 8)>>>(Wc, wch, DM, FFN);
    transpose_f16_kernel<<<dim3(FFN / 32, DM / 32), dim3(32, 8)>>>(Wg, wgh, DM, FFN);
    transpose_f16_kernel<<<dim3(DM / 32, FFN / 32), dim3(32, 8)>>>(Wd, wdh, FFN, DM);

    dtn_trop_kernel<<<dim3(FFN / 64, T_TOT / 128), 256>>>(bt);
    dtn_cg_kernel<<<dim3(FFN / 64, T_TOT / 128), 256, CG_SMEM>>>(
        sl_cvx, of_cvx, sl_ccv, of_ccv, alpha, bc, bg);
    dtn_out_kernel<<<dim3(DM / 64, T_TOT / 128), 256, OD_SMEM>>>(bd, out);
}